// round 7
// baseline (speedup 1.0000x reference)
#include <cuda_runtime.h>
#include <cstdint>

// Problem constants (fixed shapes)
#define VF    128            // V*F = 8*16
#define CCH   1024
#define HH    14
#define WW    14
#define NBOX  768
#define GG    8              // grid = OUT_SIZE+1
#define OUTS  7
#define CHT   32             // channels per block tile
#define TILES (CCH / CHT)    // 32
#define PSTR  134            // padded plane stride; EVEN (8B cp.async)
#define SCALE (1.0f/16.0f)

#define ROI_BLOCKS   (NBOX * TILES)                      // 24576
#define SNODE_BLOCKS ((VF * CCH) / 8)                    // 16384

#define ROI_COUNT   ((size_t)NBOX * CCH * OUTS * OUTS)   // 38,535,168
#define SNODE_OFF   (ROI_COUNT)
#define FAKE_OFF    (SNODE_OFF + (size_t)VF * CCH)       // 38,666,240

__device__ __forceinline__ void cp_async8(unsigned int smem_dst, const void* gmem_src) {
    asm volatile("cp.async.ca.shared.global [%0], [%1], 8;\n"
                 :: "r"(smem_dst), "l"(gmem_src) : "memory");
}

// ---------------------------------------------------------------------------
// Fused kernel. Blocks [0, ROI_BLOCKS) do RoIAlignAvg; the rest do the
// s_node mean + fake_h_s slice.
// ---------------------------------------------------------------------------
__global__ __launch_bounds__(256, 8) void fused_kernel(
    const float* __restrict__ feat,
    const float* __restrict__ boxes,
    const int*   __restrict__ fidx,
    float*       __restrict__ out)
{
    extern __shared__ float sm[];

    if (blockIdx.x >= ROI_BLOCKS) {
        // ---------------- snode + fake_h_s branch -------------------------
        const int warp = threadIdx.x >> 5;
        const int lane = threadIdx.x & 31;
        const size_t planeidx = (size_t)(blockIdx.x - ROI_BLOCKS) * 8 + warp;

        const float* src  = feat + planeidx * (HH*WW);
        float*       fake = out + FAKE_OFF + planeidx * 144;

        float sum = 0.0f;
        #pragma unroll
        for (int k = 0; k < 7; ++k) {
            const int r = lane + k * 32;
            if (r < HH*WW) {
                const float v = src[r];
                sum += v;
                const int y = r / WW;
                const int x = r - y * WW;
                if (y >= 1 && y <= 12 && x >= 1 && x <= 12)
                    fake[(y-1)*12 + (x-1)] = v;
            }
        }
        #pragma unroll
        for (int o = 16; o; o >>= 1)
            sum += __shfl_down_sync(0xFFFFFFFFu, sum, o);
        if (lane == 0)
            out[SNODE_OFF + planeidx] = sum * (1.0f / 196.0f);
        return;
    }

    // -------------------------- RoI branch --------------------------------
    float* plane = sm;                     // CHT * PSTR floats
    float* outsm = sm + CHT * PSTR;        // CHT * 49 floats

    __shared__ float s_wy[GG];
    __shared__ int   s_oA[GG], s_oB[GG];   // row byte... element offsets

    const int tid  = threadIdx.x;
    const int warp = tid >> 5, lane = tid & 31;
    const int n    = blockIdx.x / TILES;
    const int c0   = (blockIdx.x % TILES) * CHT;

    // ---- geometry (registers + tiny smem, no extra barrier) ----
    const float bx1 = boxes[n*4+0]*SCALE, by1 = boxes[n*4+1]*SCALE;
    const float bx2 = boxes[n*4+2]*SCALE, by2 = boxes[n*4+3]*SCALE;

    const int ry0   = (int)floorf(fminf(fmaxf(by1, 0.0f), (float)(HH-1)));
    const int ylast = min((int)floorf(fminf(fmaxf(by2, 0.0f), (float)(HH-1))) + 1, HH-1);
    const int L     = (ylast - ry0 + 1) * WW;    // contiguous span, even, <= 126

    if (tid < GG) {                        // y-geometry once per block
        const float t  = (float)tid * (1.0f/7.0f);
        const float ys = fminf(fmaxf(by1 + t * (by2 - by1), 0.0f), (float)(HH-1));
        const int y0i  = (int)floorf(ys);
        const int y1i  = min(y0i + 1, HH-1);
        s_wy[tid] = ys - (float)y0i;
        s_oA[tid] = (y0i - ry0) * WW;
        s_oB[tid] = (y1i - ry0) * WW;
    }

    const int b = fidx[n];
    const float* fbase = feat + ((size_t)b * CCH + c0) * (HH*WW) + ry0 * WW;

    // ---- load phase: 8B cp.async (both sides 8B aligned), high MLP ----
    {
        const unsigned int smem_base = (unsigned int)__cvta_generic_to_shared(plane);
        const int Lp = L >> 1;                       // float2 count, <= 63
        #pragma unroll
        for (int j = 0; j < CHT / 8; ++j) {          // 4 channels per warp
            const int c = warp + j * 8;
            const float2*      src = (const float2*)(fbase + c * (HH*WW));
            const unsigned int dst = smem_base + (unsigned int)(c * PSTR) * 4u;
            #pragma unroll
            for (int k = 0; k < 2; ++k) {
                const int p = lane + k * 32;
                if (p < Lp) cp_async8(dst + (unsigned int)p * 8u, src + p);
            }
        }
        // pad: zero element [L] of each of this warp's channels so the
        // unconditional xa+1 border read sees a finite value (weight is 0).
        if (lane < CHT / 8)
            plane[(warp + lane * 8) * PSTR + L] = 0.0f;
        asm volatile("cp.async.commit_group;\n" ::: "memory");
        asm volatile("cp.async.wait_group 0;\n" ::: "memory");
    }
    __syncthreads();

    // ---- compute phase: thread = (channel, gx). Branchless inner loop. ----
    {
        const int gx    = lane & 7;
        const int chsub = lane >> 3;
        const int ch    = warp * 4 + chsub;

        const float xs0 = fminf(fmaxf(bx1 + (float)gx * (1.0f/7.0f) * (bx2 - bx1),
                                      0.0f), (float)(WW-1));
        const int   xa  = (int)floorf(xs0);
        const float wx  = xs0 - (float)xa;

        const float* plx = plane + ch * PSTR + xa;
        float*       od  = outsm + ch * (OUTS*OUTS) + gx;

        float xs_prev = 0.f;
        #pragma unroll
        for (int gy = 0; gy < GG; ++gy) {
            const float wy = s_wy[gy];
            const float* pA = plx + s_oA[gy];
            const float* pB = plx + s_oB[gy];
            const float a0 = pA[0], a1 = pA[1];
            const float b0 = pB[0], b1 = pB[1];
            const float top = a0 + wx * (a1 - a0);
            const float bot = b0 + wx * (b1 - b0);
            const float g   = top + wy * (bot - top);
            // x-pool: neighbor gx+1 within the 8-lane group
            const float gr = __shfl_down_sync(0xFFFFFFFFu, g, 1, 8);
            const float xsum = g + gr;
            if (gy > 0 && gx < OUTS)
                od[(gy-1) * OUTS] = 0.25f * (xs_prev + xsum);
            xs_prev = xsum;
        }
    }
    __syncthreads();

    // ---- store phase: vectorized contiguous coalesced copy ----
    // c0 multiple of 32 -> output byte offset multiple of 6272 -> 16B aligned
    {
        const float4* src4 = (const float4*)outsm;
        float4*       dst4 = (float4*)(out + ((size_t)n * CCH + c0) * (OUTS*OUTS));
        #pragma unroll
        for (int i = tid; i < (CHT * OUTS * OUTS) / 4; i += 256)
            dst4[i] = src4[i];
    }
}

// ---------------------------------------------------------------------------
extern "C" void kernel_launch(void* const* d_in, const int* in_sizes, int n_in,
                              void* d_out, int out_size)
{
    const float* feat  = (const float*)d_in[0];
    const float* boxes = (const float*)d_in[1];
    const int*   fidx  = (const int*)d_in[2];
    float*       out   = (float*)d_out;

    const int roi_smem = (CHT * PSTR + CHT * OUTS * OUTS) * (int)sizeof(float); // 23,424 B
    cudaFuncSetAttribute(fused_kernel,
                         cudaFuncAttributeMaxDynamicSharedMemorySize, roi_smem);

    fused_kernel<<<ROI_BLOCKS + SNODE_BLOCKS, 256, roi_smem>>>(feat, boxes, fidx, out);
}

// round 8
// speedup vs baseline: 1.1069x; 1.1069x over previous
#include <cuda_runtime.h>
#include <cstdint>

// Problem constants (fixed shapes)
#define VF    128            // V*F = 8*16
#define CCH   1024
#define HH    14
#define WW    14
#define NBOX  768
#define GG    8              // grid = OUT_SIZE+1
#define OUTS  7
#define CHT   32             // channels per block tile
#define TILES (CCH / CHT)    // 32
#define PSTR  134            // padded plane stride; EVEN (8B cp.async)
#define SCALE (1.0f/16.0f)

#define ROI_BLOCKS   (NBOX * TILES)                      // 24576
#define SNODE_BLOCKS ((VF * CCH) / 8)                    // 16384

#define ROI_COUNT   ((size_t)NBOX * CCH * OUTS * OUTS)   // 38,535,168
#define SNODE_OFF   (ROI_COUNT)
#define FAKE_OFF    (SNODE_OFF + (size_t)VF * CCH)       // 38,666,240

__device__ __forceinline__ void cp_async8(unsigned int smem_dst, const void* gmem_src) {
    asm volatile("cp.async.ca.shared.global [%0], [%1], 8;\n"
                 :: "r"(smem_dst), "l"(gmem_src) : "memory");
}

// ---------------------------------------------------------------------------
// Fused kernel. Blocks [0, ROI_BLOCKS) do RoIAlignAvg; the rest do the
// s_node mean + fake_h_s slice. RoI path is fully warp-independent:
// warp w loads, computes and stores channels 4w..4w+3 — NO __syncthreads.
// ---------------------------------------------------------------------------
__global__ __launch_bounds__(256, 8) void fused_kernel(
    const float* __restrict__ feat,
    const float* __restrict__ boxes,
    const int*   __restrict__ fidx,
    float*       __restrict__ out)
{
    extern __shared__ float sm[];

    if (blockIdx.x >= ROI_BLOCKS) {
        // ---------------- snode + fake_h_s branch -------------------------
        const int warp = threadIdx.x >> 5;
        const int lane = threadIdx.x & 31;
        const size_t planeidx = (size_t)(blockIdx.x - ROI_BLOCKS) * 8 + warp;

        const float* src  = feat + planeidx * (HH*WW);
        float*       fake = out + FAKE_OFF + planeidx * 144;

        float sum = 0.0f;
        #pragma unroll
        for (int k = 0; k < 7; ++k) {
            const int r = lane + k * 32;
            if (r < HH*WW) {
                const float v = src[r];
                sum += v;
                const int y = r / WW;
                const int x = r - y * WW;
                if (y >= 1 && y <= 12 && x >= 1 && x <= 12)
                    fake[(y-1)*12 + (x-1)] = v;
            }
        }
        #pragma unroll
        for (int o = 16; o; o >>= 1)
            sum += __shfl_down_sync(0xFFFFFFFFu, sum, o);
        if (lane == 0)
            out[SNODE_OFF + planeidx] = sum * (1.0f / 196.0f);
        return;
    }

    // -------------------------- RoI branch (warp-independent) --------------
    float* plane = sm;                     // CHT * PSTR floats
    float* outsm = sm + CHT * PSTR;        // CHT * 49 floats

    const int tid  = threadIdx.x;
    const int warp = tid >> 5, lane = tid & 31;
    const int n    = blockIdx.x / TILES;
    const int c0   = (blockIdx.x % TILES) * CHT;
    const int cw   = warp * 4;             // this warp's first channel (within tile)

    // ---- geometry in registers ----
    const float bx1 = boxes[n*4+0]*SCALE, by1 = boxes[n*4+1]*SCALE;
    const float bx2 = boxes[n*4+2]*SCALE, by2 = boxes[n*4+3]*SCALE;

    const int ry0   = (int)floorf(fminf(fmaxf(by1, 0.0f), (float)(HH-1)));
    const int ylast = min((int)floorf(fminf(fmaxf(by2, 0.0f), (float)(HH-1))) + 1, HH-1);
    const int L     = (ylast - ry0 + 1) * WW;    // contiguous span, even, <= 126

    const int b = fidx[n];
    const float* fbase = feat + ((size_t)b * CCH + c0) * (HH*WW) + ry0 * WW;

    // ---- load phase: warp loads ITS OWN 4 channels via 8B cp.async ----
    {
        const unsigned int smem_base = (unsigned int)__cvta_generic_to_shared(plane);
        const int Lp = L >> 1;                       // float2 count, <= 63
        #pragma unroll
        for (int c = 0; c < 4; ++c) {
            const float2*      src = (const float2*)(fbase + (cw + c) * (HH*WW));
            const unsigned int dst = smem_base + (unsigned int)((cw + c) * PSTR) * 4u;
            #pragma unroll
            for (int k = 0; k < 2; ++k) {
                const int p = lane + k * 32;
                if (p < Lp) cp_async8(dst + (unsigned int)p * 8u, src + p);
            }
        }
        asm volatile("cp.async.commit_group;\n" ::: "memory");
        asm volatile("cp.async.wait_group 0;\n" ::: "memory");
        __syncwarp();                                // cross-lane visibility
    }

    // ---- compute phase: thread = (channel, gx); row-cached registers ----
    {
        const int gx    = lane & 7;
        const int chsub = lane >> 3;
        const int ch    = cw + chsub;
        const float* pl = plane + ch * PSTR;

        const float xs0 = fminf(fmaxf(bx1 + (float)gx * (1.0f/7.0f) * (bx2 - bx1),
                                      0.0f), (float)(WW-1));
        const int   xa  = (int)floorf(xs0);
        const int   xb  = min(xa + 1, WW-1);
        const float wx  = xs0 - (float)xa;

        int   curA = -1, curB = -1;
        float a0 = 0.f, a1 = 0.f, b0 = 0.f, b1 = 0.f;
        float xs_prev = 0.f;

        #pragma unroll
        for (int gy = 0; gy < GG; ++gy) {
            const float ys = fminf(fmaxf(by1 + (float)gy * (1.0f/7.0f) * (by2 - by1),
                                         0.0f), (float)(HH-1));
            const int y0i = (int)floorf(ys);
            const int y1i = min(y0i + 1, HH-1);
            const float wy = ys - (float)y0i;
            const int rA = y0i - ry0;
            const int rB = y1i - ry0;
            if (rA != curA) {                 // warp-uniform branch
                if (rA == curB) { a0 = b0; a1 = b1; }
                else            { a0 = pl[rA*WW + xa]; a1 = pl[rA*WW + xb]; }
                curA = rA;
            }
            if (rB != curB) {                 // warp-uniform branch
                b0 = pl[rB*WW + xa]; b1 = pl[rB*WW + xb];
                curB = rB;
            }
            const float top = a0 + wx * (a1 - a0);
            const float bot = b0 + wx * (b1 - b0);
            const float g   = top + wy * (bot - top);
            // x-pool: neighbor gx+1 within the 8-lane group
            const float gr = __shfl_down_sync(0xFFFFFFFFu, g, 1, 8);
            const float xsum = g + gr;
            if (gy > 0 && gx < OUTS)
                outsm[ch * (OUTS*OUTS) + (gy-1) * OUTS + gx] = 0.25f * (xs_prev + xsum);
            xs_prev = xsum;
        }
        __syncwarp();
    }

    // ---- store phase: warp-local vectorized copy of its 4 channels ----
    // (n*CCH + c0 + cw) * 49 floats: 196-float multiple -> 16B aligned
    {
        const float4* src4 = (const float4*)(outsm + cw * (OUTS*OUTS));
        float4*       dst4 = (float4*)(out + ((size_t)n * CCH + c0 + cw) * (OUTS*OUTS));
        #pragma unroll
        for (int i = lane; i < 49; i += 32)          // 4*49 floats = 49 float4
            dst4[i] = src4[i];
    }
}

// ---------------------------------------------------------------------------
extern "C" void kernel_launch(void* const* d_in, const int* in_sizes, int n_in,
                              void* d_out, int out_size)
{
    const float* feat  = (const float*)d_in[0];
    const float* boxes = (const float*)d_in[1];
    const int*   fidx  = (const int*)d_in[2];
    float*       out   = (float*)d_out;

    const int roi_smem = (CHT * PSTR + CHT * OUTS * OUTS) * (int)sizeof(float); // 23,424 B
    cudaFuncSetAttribute(fused_kernel,
                         cudaFuncAttributeMaxDynamicSharedMemorySize, roi_smem);

    fused_kernel<<<ROI_BLOCKS + SNODE_BLOCKS, 256, roi_smem>>>(feat, boxes, fidx, out);
}